// round 9
// baseline (speedup 1.0000x reference)
#include <cuda_runtime.h>
#include <cuda_bf16.h>
#include <stdint.h>
#include <math.h>

#define N_NODES 20000
#define E_EDGES 320000
#define B_BATCH 128
#define IN_F    25
#define DIM     64
#define H_HEADS 8
#define ETOT    (E_EDGES + N_NODES)
#define SCAN_BLKS 20

#define NEG_INF (__int_as_float(0xff800000))

// ---------------- scratch (device globals; no runtime allocation) ----------------
__device__ unsigned int g_h0h[N_NODES * 32];                       // bf16x2 packed h0
__device__ __nv_bfloat16 g_xh[(size_t)N_NODES * H_HEADS * DIM];    // bf16: 20.5 MB
__device__ float g_as[N_NODES * H_HEADS];
__device__ float g_ad[N_NODES * H_HEADS];
__device__ int   g_off[N_NODES + 1];
__device__ int   g_pos[N_NODES];
__device__ int   g_esrc[ETOT];
__device__ __nv_bfloat16 g_aggrh[(size_t)N_NODES * H_HEADS * DIM]; // bf16: 20.5 MB
__device__ float g_out[N_NODES * DIM];
__device__ int   g_is64[2];
__device__ int   g_chainv[SCAN_BLKS];

__device__ __forceinline__ void mma_bf16(float c[4], const unsigned int a[4],
                                         const unsigned int b[2]) {
    asm volatile(
        "mma.sync.aligned.m16n8k16.row.col.f32.bf16.bf16.f32 "
        "{%0,%1,%2,%3}, {%4,%5,%6,%7}, {%8,%9}, {%0,%1,%2,%3};"
        : "+f"(c[0]), "+f"(c[1]), "+f"(c[2]), "+f"(c[3])
        : "r"(a[0]), "r"(a[1]), "r"(a[2]), "r"(a[3]), "r"(b[0]), "r"(b[1]));
}

// ---------------- dtype detection (int32 vs int64 arrays) ----------------
__global__ void k_detect(const int* ei32, const int* bt32) {
    int t = threadIdx.x;  // 256 threads
    int nz = (ei32[2 * t + 1] != 0) ? 1 : 0;
    int any_e = __syncthreads_or(nz);
    int nzb = (bt32[10000 + 2 * t + 1] != 0) ? 1 : 0;
    int any_b = __syncthreads_or(nzb);
    if (t == 0) { g_is64[0] = any_e ? 0 : 1; g_is64[1] = any_b ? 0 : 1; }
}

__device__ __forceinline__ int ld_idx(const void* p, long i, int is64) {
    return is64 ? (int)((const long long*)p)[i] : ((const int*)p)[i];
}

// ---------------- h0 = relu(x @ W0 + b0), packed bf16 output ----------------
__global__ void k_lin0(const float* __restrict__ x, const float* __restrict__ W0,
                       const float* __restrict__ b0) {
    __shared__ float sW[IN_F * DIM];
    __shared__ float sb[DIM];
    int tid = threadIdx.x;
    for (int i = tid; i < IN_F * DIM; i += 256) sW[i] = W0[i];
    if (tid < DIM) sb[tid] = b0[tid];
    __syncthreads();
    int idx = blockIdx.x * 256 + tid;  // over N*32 pairs
    if (idx < N_NODES * 32) {
        int n = idx >> 5, p = idx & 31;
        int c0 = 2 * p;
        float a0 = sb[c0], a1 = sb[c0 + 1];
        const float* xr = &x[n * IN_F];
        #pragma unroll
        for (int k = 0; k < IN_F; k++) {
            float xv = xr[k];
            a0 += xv * sW[k * DIM + c0];
            a1 += xv * sW[k * DIM + c0 + 1];
        }
        __nv_bfloat162 h2 = __floats2bfloat162_rn(fmaxf(a0, 0.f), fmaxf(a1, 0.f));
        g_h0h[n * 32 + p] = *(unsigned int*)&h2;
    }
}

// ---------------- xh = h0 @ Wg (bf16 mma, bf16 out) + fused a_s/a_d dots ----------------
// grid (8 heads, 157 row-tiles), 256 threads (8 warps, 4x2 warp grid), BM=128 BN=64 K=64
#define LDAP 33   // A bf16-pair stride (32 pairs + pad)
#define LDBP 65   // B pair stride along k
#define LDC  66
__global__ void k_gemm_xh(const float* __restrict__ Wg, const float* __restrict__ att_src,
                          const float* __restrict__ att_dst) {
    const int h  = blockIdx.x;
    const int m0 = blockIdx.y * 128;
    const int tid = threadIdx.x;
    __shared__ unsigned int pool[128 * LDC];      // As32 | Bs32 ; Cs overlays all
    unsigned int* As32 = pool;                    // 128 * 33
    unsigned int* Bs32 = pool + 128 * LDAP;       // 32 * 65
    float* Cs = (float*)pool;
    __shared__ float sAs[64], sAd[64];

    if (tid < 64) sAs[tid] = att_src[h * 64 + tid];
    else if (tid < 128) sAd[tid - 64] = att_dst[h * 64 + tid - 64];

    // Load B: Wg fp32 [64][512] head block -> bf16 k-pairs Bs32[kp*LDBP + n]
    #pragma unroll
    for (int l = 0; l < 8; l++) {
        int lin = l * 256 + tid;
        int kp = lin >> 6, n = lin & 63;
        float w0 = Wg[(2 * kp) * 512 + h * 64 + n];
        float w1 = Wg[(2 * kp + 1) * 512 + h * 64 + n];
        __nv_bfloat162 p2 = __floats2bfloat162_rn(w0, w1);
        Bs32[kp * LDBP + n] = *(unsigned int*)&p2;
    }
    // Load A: bf16 rows of g_h0h, 2 threads per row, 4 uint4 each
    {
        int r = tid >> 1, half = tid & 1;
        int row = m0 + r;
        if (row < N_NODES) {
            const uint4* src = (const uint4*)&g_h0h[row * 32 + half * 16];
            #pragma unroll
            for (int q = 0; q < 4; q++) {
                uint4 v = src[q];
                int p = half * 16 + q * 4;
                As32[r * LDAP + p + 0] = v.x;
                As32[r * LDAP + p + 1] = v.y;
                As32[r * LDAP + p + 2] = v.z;
                As32[r * LDAP + p + 3] = v.w;
            }
        } else {
            #pragma unroll
            for (int q = 0; q < 16; q++) As32[r * LDAP + half * 16 + q] = 0u;
        }
    }
    __syncthreads();

    const int wid = tid >> 5, lane = tid & 31;
    const int mW = (wid >> 1) * 32, nW = (wid & 1) * 32;
    const int g = lane >> 2, tg = lane & 3;

    float c[2][4][4] = {};
    #pragma unroll
    for (int kq = 0; kq < 4; kq++) {   // 16 k per step
        int kp0 = kq * 8;
        unsigned int a[2][4], b[4][2];
        #pragma unroll
        for (int mi = 0; mi < 2; mi++) {
            int r0 = mW + mi * 16 + g;
            a[mi][0] = As32[(r0)     * LDAP + kp0 + tg];
            a[mi][1] = As32[(r0 + 8) * LDAP + kp0 + tg];
            a[mi][2] = As32[(r0)     * LDAP + kp0 + tg + 4];
            a[mi][3] = As32[(r0 + 8) * LDAP + kp0 + tg + 4];
        }
        #pragma unroll
        for (int ni = 0; ni < 4; ni++) {
            int cn = nW + ni * 8 + g;
            b[ni][0] = Bs32[(kp0 + tg)     * LDBP + cn];
            b[ni][1] = Bs32[(kp0 + tg + 4) * LDBP + cn];
        }
        #pragma unroll
        for (int mi = 0; mi < 2; mi++)
            #pragma unroll
            for (int ni = 0; ni < 4; ni++) mma_bf16(c[mi][ni], a[mi], b[ni]);
    }
    __syncthreads();

    // store C tile to smem (overlays As/Bs)
    #pragma unroll
    for (int mi = 0; mi < 2; mi++) {
        int rA = mW + mi * 16 + g;
        #pragma unroll
        for (int ni = 0; ni < 4; ni++) {
            int c0 = nW + ni * 8 + tg * 2;
            *(float2*)&Cs[(rA)     * LDC + c0] = make_float2(c[mi][ni][0], c[mi][ni][1]);
            *(float2*)&Cs[(rA + 8) * LDC + c0] = make_float2(c[mi][ni][2], c[mi][ni][3]);
        }
    }
    __syncthreads();

    // epilogue: 2 threads per row; bf16 pack + per-head att dots
    {
        int r = tid >> 1, half = tid & 1;
        int row = m0 + r;
        int cb = half * 32;
        float ps = 0.f, pd = 0.f;
        if (row < N_NODES) {
            #pragma unroll
            for (int q = 0; q < 4; q++) {       // 4 x uint4 (8 bf16 each)
                union { __nv_bfloat162 h2[4]; uint4 u; } pk;
                #pragma unroll
                for (int e = 0; e < 4; e++) {
                    float v0 = Cs[r * LDC + cb + q * 8 + 2 * e];
                    float v1 = Cs[r * LDC + cb + q * 8 + 2 * e + 1];
                    pk.h2[e] = __floats2bfloat162_rn(v0, v1);
                    ps += v0 * sAs[cb + q * 8 + 2 * e] + v1 * sAs[cb + q * 8 + 2 * e + 1];
                    pd += v0 * sAd[cb + q * 8 + 2 * e] + v1 * sAd[cb + q * 8 + 2 * e + 1];
                }
                *(uint4*)&g_xh[(size_t)row * 512 + h * 64 + cb + q * 8] = pk.u;
            }
        }
        ps += __shfl_xor_sync(0xffffffffu, ps, 1);
        pd += __shfl_xor_sync(0xffffffffu, pd, 1);
        if (half == 0 && row < N_NODES) {
            g_as[row * 8 + h] = ps;
            g_ad[row * 8 + h] = pd;
        }
    }
}

// ---------------- CSR build (by dst, incl. self-loops) ----------------
__global__ void k_hist(const void* ei) {
    int base = blockIdx.x * 1024 + threadIdx.x;
    int is64 = g_is64[0];
    #pragma unroll
    for (int u = 0; u < 4; u++) {
        int e = base + u * 256;
        if (e < E_EDGES) {
            int dst = ld_idx(ei, (long)E_EDGES + e, is64);
            atomicAdd(&g_off[dst + 1], 1);
        }
    }
}

// Phase A: per-block local inclusive scan of (deg + 1); block totals to g_chainv.
__global__ void k_scanA() {
    int b = blockIdx.x, t = threadIdx.x;
    int i = b * 1024 + t;
    int v = (i < N_NODES) ? (g_off[i + 1] + 1) : 0;
    int lane = t & 31, w = t >> 5;
    int x = v;
    #pragma unroll
    for (int d = 1; d < 32; d <<= 1) {
        int y = __shfl_up_sync(0xffffffffu, x, d);
        if (lane >= d) x += y;
    }
    __shared__ int wsum[32];
    if (lane == 31) wsum[w] = x;
    __syncthreads();
    if (w == 0) {
        int y = wsum[lane];
        #pragma unroll
        for (int d = 1; d < 32; d <<= 1) {
            int z = __shfl_up_sync(0xffffffffu, y, d);
            if (lane >= d) y += z;
        }
        wsum[lane] = y;
    }
    __syncthreads();
    int incl = x + (w > 0 ? wsum[w - 1] : 0);
    if (t == 1023) g_chainv[b] = incl;
    if (i < N_NODES) {
        g_off[i + 1] = incl;   // block-local inclusive, base added in phase C
        g_pos[i] = v;          // stash deg+1
    }
}

// Phase C: each block sums prior block totals (<=20 adds), finalizes g_off/g_pos.
__global__ void k_scanC() {
    int b = blockIdx.x, t = threadIdx.x;
    __shared__ int sbase;
    if (t == 0) {
        int base = 0;
        for (int q = 0; q < b; q++) base += g_chainv[q];
        sbase = base;
    }
    __syncthreads();
    int i = b * 1024 + t;
    if (i < N_NODES) {
        int f = g_off[i + 1] + sbase;
        g_off[i + 1] = f;
        g_pos[i] = f - g_pos[i];
    }
}

__global__ void k_scatter(const void* ei) {
    int t = blockIdx.x * 256 + threadIdx.x;
    int is64 = g_is64[0];
    if (t < E_EDGES) {
        int src = ld_idx(ei, t, is64);
        int dst = ld_idx(ei, (long)E_EDGES + t, is64);
        int slot = atomicAdd(&g_pos[dst], 1);
        g_esrc[slot] = src;
    } else if (t < E_EDGES + N_NODES) {
        int n = t - E_EDGES;
        int slot = atomicAdd(&g_pos[n], 1);
        g_esrc[slot] = n;  // self-loop
    }
}

// ---------------- per-dst online softmax + aggregation (bf16 gather, bf16 out) --------
// grid 20000 blocks, 64 threads: head = tid>>3, 8 ch/thread; depth-2 pipeline
__global__ void k_agg(const float* __restrict__ bg) {
    int nid = blockIdx.x;
    int tid = threadIdx.x;
    int h = tid >> 3, cg = tid & 7;
    float adh = g_ad[nid * 8 + h];
    int beg = g_off[nid], end = g_off[nid + 1];
    float m = NEG_INF, s = 0.f;
    float a[8] = {};
    const uint4* xh4 = (const uint4*)g_xh;
    int lane_off = h * 8 + cg;

    // prologue: edges j, j+1 in flight
    int s0 = g_esrc[beg];
    float as0 = g_as[s0 * 8 + h];
    uint4 v0 = xh4[(size_t)s0 * 64 + lane_off];
    float as1 = 0.f; uint4 v1 = make_uint4(0, 0, 0, 0);
    if (beg + 1 < end) {
        int s1 = g_esrc[beg + 1];
        as1 = g_as[s1 * 8 + h];
        v1 = xh4[(size_t)s1 * 64 + lane_off];
    }
    for (int j = beg; j < end; j++) {
        float as2 = 0.f; uint4 v2 = make_uint4(0, 0, 0, 0);
        if (j + 2 < end) {
            int s2 = g_esrc[j + 2];
            as2 = g_as[s2 * 8 + h];
            v2 = xh4[(size_t)s2 * 64 + lane_off];
        }
        float e = as0 + adh;
        e = (e > 0.f) ? e : 0.2f * e;
        float mn = fmaxf(m, e);
        float wo = __expf(m - mn);
        float we = __expf(e - mn);
        union { uint4 u; __nv_bfloat162 h2[4]; } cv;
        cv.u = v0;
        s = s * wo + we;
        #pragma unroll
        for (int q = 0; q < 4; q++) {
            float2 f = __bfloat1622float2(cv.h2[q]);
            a[2 * q]     = a[2 * q]     * wo + we * f.x;
            a[2 * q + 1] = a[2 * q + 1] * wo + we * f.y;
        }
        m = mn;
        as0 = as1; v0 = v1;
        as1 = as2; v1 = v2;
    }
    float inv = 1.f / s;
    int c0 = h * 64 + cg * 8;
    const float4 bg0 = *(const float4*)&bg[c0];
    const float4 bg1 = *(const float4*)&bg[c0 + 4];
    union { __nv_bfloat162 h2[4]; uint4 u; } pk;
    pk.h2[0] = __floats2bfloat162_rn(fmaxf(a[0] * inv + bg0.x, 0.f),
                                     fmaxf(a[1] * inv + bg0.y, 0.f));
    pk.h2[1] = __floats2bfloat162_rn(fmaxf(a[2] * inv + bg0.z, 0.f),
                                     fmaxf(a[3] * inv + bg0.w, 0.f));
    pk.h2[2] = __floats2bfloat162_rn(fmaxf(a[4] * inv + bg1.x, 0.f),
                                     fmaxf(a[5] * inv + bg1.y, 0.f));
    pk.h2[3] = __floats2bfloat162_rn(fmaxf(a[6] * inv + bg1.z, 0.f),
                                     fmaxf(a[7] * inv + bg1.w, 0.f));
    *(uint4*)&g_aggrh[(size_t)nid * 512 + c0] = pk.u;
}

// ---------------- out = relu(aggr @ Wh + bh), bf16 mma. M=20000 N=64 K=512 ----
// grid 157 (BM=128), 256 threads (8 warps, 4x2 warp grid)
__global__ void k_gemm_out(const float* __restrict__ Wh, const float* __restrict__ bh) {
    const int m0 = blockIdx.x * 128;
    const int tid = threadIdx.x;
    __shared__ unsigned int As32[128 * LDAP];  // 128 rows x 32 bf16-pairs
    __shared__ unsigned int Bs32[32 * LDBP];   // 32 k-pairs x 64 cols
    const int wid = tid >> 5, lane = tid & 31;
    const int mW = (wid >> 1) * 32, nW = (wid & 1) * 32;
    const int g = lane >> 2, tg = lane & 3;
    float c[2][4][4] = {};

    for (int kk = 0; kk < 512; kk += 64) {
        {   // load A 128x64 bf16 chunk: 2 threads per row
            int r = tid >> 1, half = tid & 1;
            int row = m0 + r;
            if (row < N_NODES) {
                const uint4* src = (const uint4*)&g_aggrh[(size_t)row * 512 + kk + half * 32];
                #pragma unroll
                for (int q = 0; q < 4; q++) {
                    uint4 v = src[q];
                    int p = half * 16 + q * 4;
                    As32[r * LDAP + p + 0] = v.x;
                    As32[r * LDAP + p + 1] = v.y;
                    As32[r * LDAP + p + 2] = v.z;
                    As32[r * LDAP + p + 3] = v.w;
                }
            } else {
                #pragma unroll
                for (int q = 0; q < 16; q++) As32[r * LDAP + half * 16 + q] = 0u;
            }
        }
        #pragma unroll
        for (int l = 0; l < 8; l++) {   // load B 64x64 chunk as k-pairs
            int lin = l * 256 + tid;
            int kp = lin >> 6, n = lin & 63;
            float w0 = Wh[(kk + 2 * kp) * 64 + n];
            float w1 = Wh[(kk + 2 * kp + 1) * 64 + n];
            __nv_bfloat162 p2 = __floats2bfloat162_rn(w0, w1);
            Bs32[kp * LDBP + n] = *(unsigned int*)&p2;
        }
        __syncthreads();
        #pragma unroll
        for (int kq = 0; kq < 4; kq++) {    // 16 k per iter
            int kp0 = kq * 8;
            unsigned int a[2][4], b[4][2];
            #pragma unroll
            for (int mi = 0; mi < 2; mi++) {
                int r0 = mW + mi * 16 + g;
                a[mi][0] = As32[(r0)     * LDAP + kp0 + tg];
                a[mi][1] = As32[(r0 + 8) * LDAP + kp0 + tg];
                a[mi][2] = As32[(r0)     * LDAP + kp0 + tg + 4];
                a[mi][3] = As32[(r0 + 8) * LDAP + kp0 + tg + 4];
            }
            #pragma unroll
            for (int ni = 0; ni < 4; ni++) {
                int cn = nW + ni * 8 + g;
                b[ni][0] = Bs32[(kp0 + tg)     * LDBP + cn];
                b[ni][1] = Bs32[(kp0 + tg + 4) * LDBP + cn];
            }
            #pragma unroll
            for (int mi = 0; mi < 2; mi++)
                #pragma unroll
                for (int ni = 0; ni < 4; ni++) mma_bf16(c[mi][ni], a[mi], b[ni]);
        }
        __syncthreads();
    }

    float2 bh2[4];
    #pragma unroll
    for (int ni = 0; ni < 4; ni++) bh2[ni] = *(const float2*)&bh[nW + ni * 8 + tg * 2];
    #pragma unroll
    for (int mi = 0; mi < 2; mi++) {
        int rA = m0 + mW + mi * 16 + g;
        #pragma unroll
        for (int ni = 0; ni < 4; ni++) {
            int col = nW + ni * 8 + tg * 2;
            if (rA < N_NODES) {
                float2 o = make_float2(fmaxf(c[mi][ni][0] + bh2[ni].x, 0.f),
                                       fmaxf(c[mi][ni][1] + bh2[ni].y, 0.f));
                *(float2*)&g_out[rA * 64 + col] = o;
            }
            if (rA + 8 < N_NODES) {
                float2 o = make_float2(fmaxf(c[mi][ni][2] + bh2[ni].x, 0.f),
                                       fmaxf(c[mi][ni][3] + bh2[ni].y, 0.f));
                *(float2*)&g_out[(rA + 8) * 64 + col] = o;
            }
        }
    }
}

__device__ __forceinline__ float sigmoidf_(float x) { return 1.f / (1.f + __expf(-x)); }

// ---------------- fused Set2Set (3 steps) + final MLP; warp-per-node attention --------
__global__ void k_s2s(const void* bt,
                      const float* __restrict__ W_ih, const float* __restrict__ W_hh,
                      const float* __restrict__ b_ih, const float* __restrict__ b_hh,
                      const float* __restrict__ W1, const float* __restrict__ b1,
                      const float* __restrict__ W2, const float* __restrict__ b2,
                      float* __restrict__ out) {
    int b = blockIdx.x, tid = threadIdx.x;
    int warp = tid >> 5, lane = tid & 31;
    __shared__ float sq[128], sh[64], sc[64], gsh[256];
    __shared__ float wm_[8], ws_[8], wr_[8][64];
    __shared__ float fin[2];
    __shared__ int sbnd[2];
    if (tid < 2) {
        int target = b + tid;
        int is64 = g_is64[1];
        int lo = 0, hi = N_NODES;
        while (lo < hi) {
            int mid = (lo + hi) >> 1;
            int v = ld_idx(bt, mid, is64);
            if (v < target) lo = mid + 1; else hi = mid;
        }
        sbnd[tid] = lo;
    }
    if (tid < 128) sq[tid] = 0.f;
    if (tid < 64) { sh[tid] = 0.f; sc[tid] = 0.f; }
    __syncthreads();
    int beg = sbnd[0], end = sbnd[1];

    for (int step = 0; step < 3; step++) {
        // ---- LSTM cell ----
        float acc = b_ih[tid] + b_hh[tid];
        const float* wi = &W_ih[tid * 128];
        #pragma unroll 4
        for (int k = 0; k < 128; k++) acc += sq[k] * wi[k];
        const float* wh = &W_hh[tid * 64];
        #pragma unroll 4
        for (int k = 0; k < 64; k++) acc += sh[k] * wh[k];
        gsh[tid] = acc;
        __syncthreads();
        if (tid < 64) {
            float ig = sigmoidf_(gsh[tid]);
            float fg = sigmoidf_(gsh[64 + tid]);
            float gg = tanhf(gsh[128 + tid]);
            float og = sigmoidf_(gsh[192 + tid]);
            float cv = fg * sc[tid] + ig * gg;
            sc[tid] = cv;
            sh[tid] = og * tanhf(cv);
        }
        __syncthreads();
        // ---- attention, warp-per-node, no block sync in loop ----
        float2 q2 = *(const float2*)&sh[2 * lane];
        float m = NEG_INF, s = 0.f;
        float2 r2 = make_float2(0.f, 0.f);
        int i = beg + warp;
        float2 v = (i < end) ? *(const float2*)&g_out[(size_t)i * 64 + 2 * lane]
                             : make_float2(0.f, 0.f);
        for (; i < end; i += 8) {
            int inext = i + 8;
            float2 vn = (inext < end) ? *(const float2*)&g_out[(size_t)inext * 64 + 2 * lane]
                                      : make_float2(0.f, 0.f);
            float p = v.x * q2.x + v.y * q2.y;
            #pragma unroll
            for (int off = 16; off; off >>= 1) p += __shfl_xor_sync(0xffffffffu, p, off);
            float mn = fmaxf(m, p);
            float wo = __expf(m - mn);
            float we = __expf(p - mn);
            s = s * wo + we;
            r2.x = r2.x * wo + we * v.x;
            r2.y = r2.y * wo + we * v.y;
            m = mn;
            v = vn;
        }
        if (lane == 0) { wm_[warp] = m; ws_[warp] = s; }
        wr_[warp][2 * lane] = r2.x;
        wr_[warp][2 * lane + 1] = r2.y;
        __syncthreads();
        if (tid < 64) {
            float M = NEG_INF;
            #pragma unroll
            for (int w = 0; w < 8; w++) M = fmaxf(M, wm_[w]);
            float S = 0.f, R = 0.f;
            #pragma unroll
            for (int w = 0; w < 8; w++) {
                float f = (wm_[w] == NEG_INF) ? 0.f : __expf(wm_[w] - M);
                S += ws_[w] * f;
                R += wr_[w][tid] * f;
            }
            float r = (S > 0.f) ? (R / S) : 0.f;
            sq[tid] = sh[tid];
            sq[64 + tid] = r;
        }
        __syncthreads();
    }
    // ---- final MLP ----
    if (tid < 64) {
        float acc = b1[tid];
        #pragma unroll 4
        for (int k = 0; k < 128; k++) acc += sq[k] * W1[k * 64 + tid];
        acc = fmaxf(acc, 0.f);
        float z = acc * W2[tid];
        #pragma unroll
        for (int off = 16; off; off >>= 1) z += __shfl_down_sync(0xffffffffu, z, off);
        if ((tid & 31) == 0) fin[tid >> 5] = z;
    }
    __syncthreads();
    if (tid == 0) out[b] = fin[0] + fin[1] + b2[0];
}

// ---------------- orchestration: two-stream fork (CSR build || feature GEMMs) --------
extern "C" void kernel_launch(void* const* d_in, const int* in_sizes, int n_in,
                              void* d_out, int out_size) {
    const float* x   = (const float*)d_in[0];
    const void*  ei  = d_in[1];
    const void*  bt  = d_in[2];
    const float* W0  = (const float*)d_in[3];
    const float* b0  = (const float*)d_in[4];
    const float* Wg  = (const float*)d_in[5];
    const float* asr = (const float*)d_in[6];
    const float* ads = (const float*)d_in[7];
    const float* bg  = (const float*)d_in[8];
    const float* Wh  = (const float*)d_in[9];
    const float* bh  = (const float*)d_in[10];
    const float* Wih = (const float*)d_in[11];
    const float* Whh = (const float*)d_in[12];
    const float* bih = (const float*)d_in[13];
    const float* bhh = (const float*)d_in[14];
    const float* W1  = (const float*)d_in[15];
    const float* b1  = (const float*)d_in[16];
    const float* W2  = (const float*)d_in[17];
    const float* b2  = (const float*)d_in[18];
    float* out = (float*)d_out;

    static cudaStream_t s1 = nullptr, s2 = nullptr;
    static cudaEvent_t evA = nullptr, evB = nullptr, evC = nullptr;
    if (s1 == nullptr) {
        cudaStreamCreateWithFlags(&s1, cudaStreamNonBlocking);
        cudaStreamCreateWithFlags(&s2, cudaStreamNonBlocking);
        cudaEventCreateWithFlags(&evA, cudaEventDisableTiming);
        cudaEventCreateWithFlags(&evB, cudaEventDisableTiming);
        cudaEventCreateWithFlags(&evC, cudaEventDisableTiming);
    }

    void* off_ptr = nullptr;
    cudaGetSymbolAddress(&off_ptr, g_off);

    k_detect<<<1, 256>>>((const int*)ei, (const int*)bt);
    cudaEventRecord(evA, 0);
    cudaStreamWaitEvent(s1, evA, 0);
    cudaStreamWaitEvent(s2, evA, 0);

    // branch 1: feature path
    k_lin0<<<(N_NODES * 32 + 255) / 256, 256, 0, s1>>>(x, W0, b0);
    k_gemm_xh<<<dim3(8, (N_NODES + 127) / 128), 256, 0, s1>>>(Wg, asr, ads);
    cudaEventRecord(evB, s1);

    // branch 2: CSR build
    cudaMemsetAsync(off_ptr, 0, (N_NODES + 1) * sizeof(int), s2);
    k_hist<<<(E_EDGES + 1023) / 1024, 256, 0, s2>>>(ei);
    k_scanA<<<SCAN_BLKS, 1024, 0, s2>>>();
    k_scanC<<<SCAN_BLKS, 1024, 0, s2>>>();
    k_scatter<<<(E_EDGES + N_NODES + 255) / 256, 256, 0, s2>>>(ei);
    cudaEventRecord(evC, s2);

    // join
    cudaStreamWaitEvent(0, evB, 0);
    cudaStreamWaitEvent(0, evC, 0);

    k_agg<<<N_NODES, 64>>>(bg);
    k_gemm_out<<<(N_NODES + 127) / 128, 256>>>(Wh, bh);
    k_s2s<<<B_BATCH, 256>>>(bt, Wih, Whh, bih, bhh, W1, b1, W2, b2, out);
}